// round 4
// baseline (speedup 1.0000x reference)
#include <cuda_runtime.h>
#include <cstdint>
#include <cstddef>

// Problem constants
#define Bb   64
#define Tt   512
#define Dd   512
#define Uu   1024
#define NG   4096          // 4*U
#define BT   (Bb * Tt)     // 32768 rows for the input-projection GEMMs
#define RGRID 128          // persistent CTAs for the recurrence (<=148 SMs -> resident)
#define UC    8            // U columns owned per CTA (128*8 = 1024)

// ---------------------------------------------------------------------------
// Scratch (device globals; no allocations allowed)
// ---------------------------------------------------------------------------
__device__ float g_zx[(size_t)BT * NG];     // z = x@W + b   (reused by both layers)
__device__ float g_h1[(size_t)BT * Uu];     // layer-1 hidden sequence (LN'd in place)
__device__ float g_hbuf[2][Uu * Bb];        // double-buffered h, layout [u][b]
__device__ float g_Rp1[(size_t)RGRID * Uu * 32];  // repacked R1: [cta][k][32]
__device__ float g_Rp2[(size_t)RGRID * Uu * 32];  // repacked R2: [cta][k][32]
__device__ unsigned g_cnt = 0;
__device__ unsigned g_gen = 0;

// ---------------------------------------------------------------------------
// Grid-wide barrier (all RGRID CTAs resident). Generation counter is
// monotone; counter returns to 0 -> deterministic across graph replays.
// ---------------------------------------------------------------------------
__device__ __forceinline__ void grid_sync() {
    __syncthreads();
    if (threadIdx.x == 0) {
        __threadfence();
        unsigned gen = atomicAdd(&g_gen, 0u);   // snapshot generation
        __threadfence();                         // order snapshot before arrive
        if (atomicAdd(&g_cnt, 1u) == RGRID - 1u) {
            atomicExch(&g_cnt, 0u);
            __threadfence();
            atomicAdd(&g_gen, 1u);               // release
        } else {
            while (atomicAdd(&g_gen, 0u) == gen) { __nanosleep(32); }
        }
    }
    __syncthreads();
}

// ---------------------------------------------------------------------------
// Repack R[1024,4096] -> Rp[cta][k][32] so each CTA's per-k slice of 32
// z-columns (8 u-cols x 4 gates, in c4-order) is one contiguous 128B line.
// c4 = col32>>2: gate = c4>>1, quad = c4&1; j = col32&3.
// orig col = gate*1024 + cta*8 + quad*4 + j.
// ---------------------------------------------------------------------------
__global__ void __launch_bounds__(256) repack_R_kernel(
    const float* __restrict__ R, float* __restrict__ Rp)
{
    int idx = blockIdx.x * 256 + threadIdx.x;   // over RGRID*Uu*32 = 4.19M
    if (idx >= RGRID * Uu * 32) return;
    int col32 = idx & 31;
    int k     = (idx >> 5) & (Uu - 1);
    int cta   = idx >> 15;
    int c4   = col32 >> 2;
    int j    = col32 & 3;
    int gate = c4 >> 1;
    int quad = c4 & 1;
    int ocol = gate * Uu + cta * UC + quad * 4 + j;
    Rp[idx] = R[(size_t)k * NG + ocol];
}

// ---------------------------------------------------------------------------
// GEMM: g_zx[M,4096] = A[M,K] @ W[K,4096] + bias   (M = 32768)
// Tiles: 128x128x16, 256 threads, 8x8 per-thread microtile.
// A staged k-major-transposed in SMEM -> both fragments load as LDS.128,
// 4 LDS.128 per 64 FFMA in the inner loop.
// Software-pipelined: tile k+1's global loads are issued before tile k's
// compute so LDG latency drains under the FFMA block. fp32.
// ---------------------------------------------------------------------------
template <int K>
__global__ void __launch_bounds__(256, 2) gemm_bias_kernel(
    const float* __restrict__ Aext, const float* __restrict__ W,
    const float* __restrict__ bias, int use_h1)
{
    const float* __restrict__ A = use_h1 ? g_h1 : Aext;
    __shared__ float As[16][128];   // [k][m]  (transposed stage)
    __shared__ float Bs[16][128];   // [k][n]

    const int tid = threadIdx.x;
    const int n0  = blockIdx.x * 128;
    const int m0  = blockIdx.y * 128;

    const int ar = tid >> 2;           // 0..63
    const int ak = (tid & 3) * 4;      // 0,4,8,12
    const int bk = tid >> 4;           // 0..15
    const int bn = (tid & 15) * 8;     // 0..120
    const int tm = (tid >> 4) * 8;     // 0..120
    const int tn = (tid & 15) * 8;     // 0..120

    const float* pA0 = &A[(size_t)(m0 + ar) * K + ak];
    const float* pA1 = &A[(size_t)(m0 + ar + 64) * K + ak];
    const float* pW0 = &W[(size_t)bk * NG + n0 + bn];
    const float* pW1 = pW0 + 4;

    float acc[8][8];
#pragma unroll
    for (int i = 0; i < 8; i++)
#pragma unroll
        for (int j = 0; j < 8; j++) acc[i][j] = 0.f;

    // prologue: load tile 0
    float4 a0 = *(const float4*)(pA0);
    float4 a1 = *(const float4*)(pA1);
    float4 w0 = *(const float4*)(pW0);
    float4 w1 = *(const float4*)(pW1);

    for (int k0 = 0; k0 < K; k0 += 16) {
        __syncthreads();               // SMEM free from previous compute
        As[ak + 0][ar] = a0.x;  As[ak + 1][ar] = a0.y;
        As[ak + 2][ar] = a0.z;  As[ak + 3][ar] = a0.w;
        As[ak + 0][ar + 64] = a1.x;  As[ak + 1][ar + 64] = a1.y;
        As[ak + 2][ar + 64] = a1.z;  As[ak + 3][ar + 64] = a1.w;
        *(float4*)&Bs[bk][bn]     = w0;
        *(float4*)&Bs[bk][bn + 4] = w1;
        __syncthreads();

        // prefetch tile k0+16 (latency hidden under the FFMA block below)
        if (k0 + 16 < K) {
            a0 = *(const float4*)(pA0 + k0 + 16);
            a1 = *(const float4*)(pA1 + k0 + 16);
            w0 = *(const float4*)(pW0 + (size_t)(k0 + 16) * NG);
            w1 = *(const float4*)(pW1 + (size_t)(k0 + 16) * NG);
        }

#pragma unroll
        for (int kk = 0; kk < 16; kk++) {
            float4 av0 = *(const float4*)&As[kk][tm];
            float4 av1 = *(const float4*)&As[kk][tm + 4];
            float4 bv0 = *(const float4*)&Bs[kk][tn];
            float4 bv1 = *(const float4*)&Bs[kk][tn + 4];
            float a_[8] = {av0.x, av0.y, av0.z, av0.w, av1.x, av1.y, av1.z, av1.w};
            float b_[8] = {bv0.x, bv0.y, bv0.z, bv0.w, bv1.x, bv1.y, bv1.z, bv1.w};
#pragma unroll
            for (int i = 0; i < 8; i++)
#pragma unroll
                for (int j = 0; j < 8; j++)
                    acc[i][j] = fmaf(a_[i], b_[j], acc[i][j]);
        }
    }

    float4 bb0 = *(const float4*)&bias[n0 + tn];
    float4 bb1 = *(const float4*)&bias[n0 + tn + 4];
    float bbv[8] = {bb0.x, bb0.y, bb0.z, bb0.w, bb1.x, bb1.y, bb1.z, bb1.w};
#pragma unroll
    for (int i = 0; i < 8; i++) {
        float4 r0 = { acc[i][0] + bbv[0], acc[i][1] + bbv[1],
                      acc[i][2] + bbv[2], acc[i][3] + bbv[3] };
        float4 r1 = { acc[i][4] + bbv[4], acc[i][5] + bbv[5],
                      acc[i][6] + bbv[6], acc[i][7] + bbv[7] };
        *(float4*)&g_zx[(size_t)(m0 + tm + i) * NG + n0 + tn]     = r0;
        *(float4*)&g_zx[(size_t)(m0 + tm + i) * NG + n0 + tn + 4] = r1;
    }
}

// ---------------------------------------------------------------------------
// Persistent LSTM recurrence. One launch runs all T steps.
// CTA j owns u in [j*8, j*8+8): computes z-slices for all 4 gates, updates
// its c slice (SMEM-resident), publishes h transposed [u][b] for the next
// step. h reads use __ldcg (L2) because L1 is incoherent across SMs.
// R comes from the repacked g_Rp layout: warp's per-k load = one 128B line.
// Keras gate order (activation=None): i,f,g,o ; c = sig(f)*c + sig(i)*g ;
// h = sig(o)*c.
// ---------------------------------------------------------------------------
__global__ void __launch_bounds__(256) recur_kernel(
    const float* __restrict__ Rp, int store_seq)
{
    __shared__ float z_s[64][32];   // [b][gate*8 + ul]
    __shared__ float c_s[64][8];    // cell state, persists across all steps

    const int tid = threadIdx.x;
    const int cta = blockIdx.x;
    const int u_base = cta * UC;

    // init c = 0 and h buffers = 0
    for (int p = tid; p < 512; p += 256) c_s[p & 63][p >> 6] = 0.f;
    {
        float* hflat = &g_hbuf[0][0];
        for (int i = cta * 256 + tid; i < 2 * Uu * Bb; i += RGRID * 256)
            hflat[i] = 0.f;
    }
    grid_sync();

    const int b0   = (tid >> 3) * 2;   // 2 batch rows per thread
    const int c4   = tid & 7;
    const int gate = c4 >> 1;
    const int quad = c4 & 1;
    const int ncol = gate * Uu + u_base + quad * 4;  // z column in g_zx
    const float* Rb = Rp + (size_t)cta * Uu * 32 + c4 * 4;
    const int zc   = gate * 8 + quad * 4;

    for (int t = 0; t < Tt; t++) {
        const float* hp = g_hbuf[t & 1];
        float4 a0 = {0.f, 0.f, 0.f, 0.f};
        float4 a1 = {0.f, 0.f, 0.f, 0.f};
#pragma unroll 8
        for (int k = 0; k < Uu; k++) {
            float2 h2 = __ldcg((const float2*)(hp + k * Bb + b0));
            float4 r4 = *(const float4*)(Rb + (size_t)k * 32);
            a0.x = fmaf(h2.x, r4.x, a0.x);
            a0.y = fmaf(h2.x, r4.y, a0.y);
            a0.z = fmaf(h2.x, r4.z, a0.z);
            a0.w = fmaf(h2.x, r4.w, a0.w);
            a1.x = fmaf(h2.y, r4.x, a1.x);
            a1.y = fmaf(h2.y, r4.y, a1.y);
            a1.z = fmaf(h2.y, r4.z, a1.z);
            a1.w = fmaf(h2.y, r4.w, a1.w);
        }
        // add precomputed input projection zx[b, t, ncol..ncol+3]
        float4 zx0 = *(const float4*)&g_zx[((size_t)b0 * Tt + t) * NG + ncol];
        float4 zx1 = *(const float4*)&g_zx[((size_t)(b0 + 1) * Tt + t) * NG + ncol];
        z_s[b0][zc + 0] = a0.x + zx0.x;
        z_s[b0][zc + 1] = a0.y + zx0.y;
        z_s[b0][zc + 2] = a0.z + zx0.z;
        z_s[b0][zc + 3] = a0.w + zx0.w;
        z_s[b0 + 1][zc + 0] = a1.x + zx1.x;
        z_s[b0 + 1][zc + 1] = a1.y + zx1.y;
        z_s[b0 + 1][zc + 2] = a1.z + zx1.z;
        z_s[b0 + 1][zc + 3] = a1.w + zx1.w;
        __syncthreads();

        // gate math: 512 (b, ul) pairs, 2 per thread
        for (int p = tid; p < 512; p += 256) {
            int b  = p & 63;
            int ul = p >> 6;
            float zi = z_s[b][ul];
            float zf = z_s[b][8 + ul];
            float zg = z_s[b][16 + ul];
            float zo = z_s[b][24 + ul];
            float ig = 1.f / (1.f + expf(-zi));
            float fg = 1.f / (1.f + expf(-zf));
            float og = 1.f / (1.f + expf(-zo));
            float c  = fmaf(fg, c_s[b][ul], ig * zg);
            c_s[b][ul] = c;
            float h = og * c;
            g_hbuf[(t + 1) & 1][(u_base + ul) * Bb + b] = h;
            if (store_seq)
                g_h1[((size_t)b * Tt + t) * Uu + u_base + ul] = h;
        }
        grid_sync();   // publishes h for the next step; protects SMEM reuse
    }
    // final h (t = T-1) was written to g_hbuf[T & 1] = g_hbuf[0]
}

// ---------------------------------------------------------------------------
// LayerNorm over last dim (1024) + tanh.
// mode 0: in/out = g_h1 [32768,1024] row-major, in place.
// mode 1: in = g_hbuf[0] transposed [u][b]; out = external [64,1024].
// ---------------------------------------------------------------------------
__global__ void __launch_bounds__(256) ln_tanh_kernel(
    int mode, float* __restrict__ outext,
    const float* __restrict__ gamma, const float* __restrict__ beta)
{
    const int row = blockIdx.x;
    const int tid = threadIdx.x;
    const float* in;
    size_t rs, us;
    if (mode == 0) { in = g_h1;          rs = Uu; us = 1;  }
    else           { in = &g_hbuf[0][0]; rs = 1;  us = Bb; }

    float v[4];
    float s = 0.f, sq = 0.f;
#pragma unroll
    for (int i = 0; i < 4; i++) {
        int u = tid + i * 256;
        v[i] = in[(size_t)row * rs + (size_t)u * us];
        s  += v[i];
        sq += v[i] * v[i];
    }
#pragma unroll
    for (int o = 16; o; o >>= 1) {
        s  += __shfl_xor_sync(0xffffffffu, s, o);
        sq += __shfl_xor_sync(0xffffffffu, sq, o);
    }
    __shared__ float ws[8], wq[8];
    __shared__ float s_mu, s_inv;
    if ((tid & 31) == 0) { ws[tid >> 5] = s; wq[tid >> 5] = sq; }
    __syncthreads();
    if (tid == 0) {
        float ts = 0.f, tq = 0.f;
#pragma unroll
        for (int i = 0; i < 8; i++) { ts += ws[i]; tq += wq[i]; }
        float mu  = ts * (1.f / 1024.f);
        float var = tq * (1.f / 1024.f) - mu * mu;
        s_mu  = mu;
        s_inv = rsqrtf(var + 1e-3f);
    }
    __syncthreads();
    float mu = s_mu, inv = s_inv;
#pragma unroll
    for (int i = 0; i < 4; i++) {
        int u = tid + i * 256;
        float y = tanhf((v[i] - mu) * inv * gamma[u] + beta[u]);
        if (mode == 0) g_h1[(size_t)row * Uu + u] = y;
        else           outext[(size_t)row * Uu + u] = y;
    }
}

// ---------------------------------------------------------------------------
// Launch: repack R1/R2 -> GEMM1 -> recur1 -> LN1 -> GEMM2 -> recur2 -> LN2
// ---------------------------------------------------------------------------
extern "C" void kernel_launch(void* const* d_in, const int* in_sizes, int n_in,
                              void* d_out, int out_size)
{
    const float* x      = (const float*)d_in[0];
    const float* W1     = (const float*)d_in[1];
    const float* R1     = (const float*)d_in[2];
    const float* b1     = (const float*)d_in[3];
    const float* gamma1 = (const float*)d_in[4];
    const float* beta1  = (const float*)d_in[5];
    const float* W2     = (const float*)d_in[6];
    const float* R2     = (const float*)d_in[7];
    const float* b2     = (const float*)d_in[8];
    const float* gamma2 = (const float*)d_in[9];
    const float* beta2  = (const float*)d_in[10];
    float* out = (float*)d_out;

    float* Rp1;  cudaGetSymbolAddress((void**)&Rp1, g_Rp1);
    float* Rp2;  cudaGetSymbolAddress((void**)&Rp2, g_Rp2);

    const int nrep = (RGRID * Uu * 32 + 255) / 256;
    dim3 gg(NG / 128, BT / 128);

    repack_R_kernel<<<nrep, 256>>>(R1, Rp1);
    repack_R_kernel<<<nrep, 256>>>(R2, Rp2);
    gemm_bias_kernel<Dd><<<gg, 256>>>(x, W1, b1, 0);          // zx1 = x@W1 + b1
    recur_kernel<<<RGRID, 256>>>(Rp1, 1);                     // h1 sequence
    ln_tanh_kernel<<<BT, 256>>>(0, nullptr, gamma1, beta1);   // LN+tanh in place
    gemm_bias_kernel<Uu><<<gg, 256>>>(nullptr, W2, b2, 1);    // zx2 = h1n@W2 + b2
    recur_kernel<<<RGRID, 256>>>(Rp2, 0);                     // h2 final in g_hbuf[0]
    ln_tanh_kernel<<<Bb, 256>>>(1, out, gamma2, beta2);       // final LN+tanh
}

// round 7
// speedup vs baseline: 5.8956x; 5.8956x over previous
#include <cuda_runtime.h>
#include <cstdint>
#include <cstddef>

// Problem constants
#define Bb   64
#define Tt   512
#define Dd   512
#define Uu   1024
#define NG   4096          // 4*U
#define BT   (Bb * Tt)     // 32768 rows for the input-projection GEMMs
#define RGRID 128          // persistent CTAs for the recurrence (<=148 SMs -> resident)
#define UC    8            // U columns owned per CTA (128*8 = 1024)

// Dynamic SMEM for recur: R slice + padded z + padded c
#define ZPAD 33
#define CPAD 9
#define RS_FLOATS (Uu * 32)
#define ZS_FLOATS (64 * ZPAD)
#define CS_FLOATS (64 * CPAD)
#define SMEM_DYN  ((RS_FLOATS + ZS_FLOATS + CS_FLOATS) * 4)

// ---------------------------------------------------------------------------
// Scratch (device globals; no allocations allowed)
// ---------------------------------------------------------------------------
__device__ float g_zx[(size_t)BT * NG];     // z = x@W + b   (reused by both layers)
__device__ float g_h1[(size_t)BT * Uu];     // layer-1 hidden sequence (LN'd in place)
__device__ float g_hbuf[2][Uu * Bb];        // double-buffered h, layout [u][b]
__device__ unsigned g_cnt = 0;
__device__ unsigned g_gen = 0;

// ---------------------------------------------------------------------------
// Grid-wide barrier (all RGRID CTAs resident). Poll is a volatile L2 load
// (no atomic RMW serialization). Generation counter is monotone across
// graph replays; counter returns to 0 -> deterministic.
// ---------------------------------------------------------------------------
__device__ __forceinline__ void grid_sync() {
    __syncthreads();
    if (threadIdx.x == 0) {
        __threadfence();
        unsigned gen = *(volatile unsigned*)&g_gen;   // snapshot BEFORE arrive
        __threadfence();
        if (atomicAdd(&g_cnt, 1u) == RGRID - 1u) {
            *(volatile unsigned*)&g_cnt = 0u;
            __threadfence();
            atomicAdd(&g_gen, 1u);                    // release
        } else {
            while (*(volatile unsigned*)&g_gen == gen) { }
        }
        __threadfence();
    }
    __syncthreads();
}

// ---------------------------------------------------------------------------
// GEMM: g_zx[M,4096] = A[M,K] @ W[K,4096] + bias   (M = 32768)
// 128x128x16 tiles, 256 threads, 8x8 microtile, reg-prefetch pipeline. fp32.
// ---------------------------------------------------------------------------
template <int K>
__global__ void __launch_bounds__(256, 2) gemm_bias_kernel(
    const float* __restrict__ Aext, const float* __restrict__ W,
    const float* __restrict__ bias, int use_h1)
{
    const float* __restrict__ A = use_h1 ? g_h1 : Aext;
    __shared__ float As[16][128];   // [k][m]  (transposed stage)
    __shared__ float Bs[16][128];   // [k][n]

    const int tid = threadIdx.x;
    const int n0  = blockIdx.x * 128;
    const int m0  = blockIdx.y * 128;

    const int ar = tid >> 2;           // 0..63
    const int ak = (tid & 3) * 4;      // 0,4,8,12
    const int bk = tid >> 4;           // 0..15
    const int bn = (tid & 15) * 8;     // 0..120
    const int tm = (tid >> 4) * 8;     // 0..120
    const int tn = (tid & 15) * 8;     // 0..120

    const float* pA0 = &A[(size_t)(m0 + ar) * K + ak];
    const float* pA1 = &A[(size_t)(m0 + ar + 64) * K + ak];
    const float* pW0 = &W[(size_t)bk * NG + n0 + bn];
    const float* pW1 = pW0 + 4;

    float acc[8][8];
#pragma unroll
    for (int i = 0; i < 8; i++)
#pragma unroll
        for (int j = 0; j < 8; j++) acc[i][j] = 0.f;

    float4 a0 = *(const float4*)(pA0);
    float4 a1 = *(const float4*)(pA1);
    float4 w0 = *(const float4*)(pW0);
    float4 w1 = *(const float4*)(pW1);

    for (int k0 = 0; k0 < K; k0 += 16) {
        __syncthreads();
        As[ak + 0][ar] = a0.x;  As[ak + 1][ar] = a0.y;
        As[ak + 2][ar] = a0.z;  As[ak + 3][ar] = a0.w;
        As[ak + 0][ar + 64] = a1.x;  As[ak + 1][ar + 64] = a1.y;
        As[ak + 2][ar + 64] = a1.z;  As[ak + 3][ar + 64] = a1.w;
        *(float4*)&Bs[bk][bn]     = w0;
        *(float4*)&Bs[bk][bn + 4] = w1;
        __syncthreads();

        if (k0 + 16 < K) {
            a0 = *(const float4*)(pA0 + k0 + 16);
            a1 = *(const float4*)(pA1 + k0 + 16);
            w0 = *(const float4*)(pW0 + (size_t)(k0 + 16) * NG);
            w1 = *(const float4*)(pW1 + (size_t)(k0 + 16) * NG);
        }

#pragma unroll
        for (int kk = 0; kk < 16; kk++) {
            float4 av0 = *(const float4*)&As[kk][tm];
            float4 av1 = *(const float4*)&As[kk][tm + 4];
            float4 bv0 = *(const float4*)&Bs[kk][tn];
            float4 bv1 = *(const float4*)&Bs[kk][tn + 4];
            float a_[8] = {av0.x, av0.y, av0.z, av0.w, av1.x, av1.y, av1.z, av1.w};
            float b_[8] = {bv0.x, bv0.y, bv0.z, bv0.w, bv1.x, bv1.y, bv1.z, bv1.w};
#pragma unroll
            for (int i = 0; i < 8; i++)
#pragma unroll
                for (int j = 0; j < 8; j++)
                    acc[i][j] = fmaf(a_[i], b_[j], acc[i][j]);
        }
    }

    float4 bb0 = *(const float4*)&bias[n0 + tn];
    float4 bb1 = *(const float4*)&bias[n0 + tn + 4];
    float bbv[8] = {bb0.x, bb0.y, bb0.z, bb0.w, bb1.x, bb1.y, bb1.z, bb1.w};
#pragma unroll
    for (int i = 0; i < 8; i++) {
        float4 r0 = { acc[i][0] + bbv[0], acc[i][1] + bbv[1],
                      acc[i][2] + bbv[2], acc[i][3] + bbv[3] };
        float4 r1 = { acc[i][4] + bbv[4], acc[i][5] + bbv[5],
                      acc[i][6] + bbv[6], acc[i][7] + bbv[7] };
        *(float4*)&g_zx[(size_t)(m0 + tm + i) * NG + n0 + tn]     = r0;
        *(float4*)&g_zx[(size_t)(m0 + tm + i) * NG + n0 + tn + 4] = r1;
    }
}

// ---------------------------------------------------------------------------
// Persistent LSTM recurrence, v3b.
// - CTA's R slice (time-invariant, 128KB) gathered into SMEM ONCE; inner
//   loop reads it via conflict-free LDS.128.
// - h loads (L2, __ldcg) double-buffered 16-deep in registers -> the L2
//   latency (~250cyc) is covered with 2x margin under each 128-FFMA block.
// - zs/cs padded (33/9) -> conflict-free gate phase.
// - gate phase: thread owns (b, u-pair) -> float2 store into g_h1.
// Keras gate order (activation=None): i,f,g,o ; c = sig(f)*c + sig(i)*g ;
// h = sig(o)*c.
// ---------------------------------------------------------------------------
__global__ void __launch_bounds__(256, 1) recur_kernel(
    const float* __restrict__ Rw, int store_seq)
{
    extern __shared__ float smem[];
    float* Rs = smem;                       // [k][32]
    float* zs = smem + RS_FLOATS;           // [b][ZPAD]
    float* cs = zs + ZS_FLOATS;             // [b][CPAD]

    const int tid = threadIdx.x;
    const int cta = blockIdx.x;
    const int u_base = cta * UC;

    // gather this CTA's R slice into SMEM: Rs[k*32 + col32]
    // col32 -> c4 = col32>>2 (gate = c4>>1, quad = c4&1), j = col32&3
    for (int idx = tid; idx < RS_FLOATS; idx += 256) {
        int col32 = idx & 31;
        int k     = idx >> 5;
        int c4i   = col32 >> 2;
        int j     = col32 & 3;
        int gate  = c4i >> 1;
        int quad  = c4i & 1;
        Rs[idx] = Rw[(size_t)k * NG + gate * Uu + u_base + quad * 4 + j];
    }
    // init c = 0 and h buffers = 0
    for (int p = tid; p < CS_FLOATS; p += 256) cs[p] = 0.f;
    {
        float* hflat = &g_hbuf[0][0];
        for (int i = cta * 256 + tid; i < 2 * Uu * Bb; i += RGRID * 256)
            hflat[i] = 0.f;
    }
    grid_sync();   // also orders Rs/cs for all threads

    const int b0   = (tid >> 3) * 2;   // 2 batch rows per thread (GEMM phase)
    const int c4   = tid & 7;
    const int gate = c4 >> 1;
    const int quad = c4 & 1;
    const int ncol = gate * Uu + u_base + quad * 4;  // z column in g_zx
    const int c4q  = c4 * 4;
    const int zc   = gate * 8 + quad * 4;

    // gate-phase mapping: thread owns batch gb and u-pair gu (=2 consecutive u)
    const int gb = tid & 63;
    const int gu = (tid >> 6) * 2;

    for (int t = 0; t < Tt; t++) {
        const float* hp = g_hbuf[t & 1];
        // zx loads issued early (DRAM), consumed after the k-loop
        float4 zx0 = *(const float4*)&g_zx[((size_t)b0 * Tt + t) * NG + ncol];
        float4 zx1 = *(const float4*)&g_zx[((size_t)(b0 + 1) * Tt + t) * NG + ncol];

        float4 a0 = {0.f, 0.f, 0.f, 0.f};
        float4 a1 = {0.f, 0.f, 0.f, 0.f};

        float2 hA[16], hB[16];
#pragma unroll
        for (int j = 0; j < 16; j++)
            hA[j] = __ldcg((const float2*)(hp + j * Bb + b0));

        for (int k0 = 0; k0 < Uu; k0 += 32) {
#pragma unroll
            for (int j = 0; j < 16; j++)
                hB[j] = __ldcg((const float2*)(hp + (k0 + 16 + j) * Bb + b0));
#pragma unroll
            for (int j = 0; j < 16; j++) {
                float4 r4 = *(const float4*)&Rs[(k0 + j) * 32 + c4q];
                float2 h2 = hA[j];
                a0.x = fmaf(h2.x, r4.x, a0.x);
                a0.y = fmaf(h2.x, r4.y, a0.y);
                a0.z = fmaf(h2.x, r4.z, a0.z);
                a0.w = fmaf(h2.x, r4.w, a0.w);
                a1.x = fmaf(h2.y, r4.x, a1.x);
                a1.y = fmaf(h2.y, r4.y, a1.y);
                a1.z = fmaf(h2.y, r4.z, a1.z);
                a1.w = fmaf(h2.y, r4.w, a1.w);
            }
            if (k0 + 32 < Uu) {
#pragma unroll
                for (int j = 0; j < 16; j++)
                    hA[j] = __ldcg((const float2*)(hp + (k0 + 32 + j) * Bb + b0));
            }
#pragma unroll
            for (int j = 0; j < 16; j++) {
                float4 r4 = *(const float4*)&Rs[(k0 + 16 + j) * 32 + c4q];
                float2 h2 = hB[j];
                a0.x = fmaf(h2.x, r4.x, a0.x);
                a0.y = fmaf(h2.x, r4.y, a0.y);
                a0.z = fmaf(h2.x, r4.z, a0.z);
                a0.w = fmaf(h2.x, r4.w, a0.w);
                a1.x = fmaf(h2.y, r4.x, a1.x);
                a1.y = fmaf(h2.y, r4.y, a1.y);
                a1.z = fmaf(h2.y, r4.z, a1.z);
                a1.w = fmaf(h2.y, r4.w, a1.w);
            }
        }

        zs[b0 * ZPAD + zc + 0] = a0.x + zx0.x;
        zs[b0 * ZPAD + zc + 1] = a0.y + zx0.y;
        zs[b0 * ZPAD + zc + 2] = a0.z + zx0.z;
        zs[b0 * ZPAD + zc + 3] = a0.w + zx0.w;
        zs[(b0 + 1) * ZPAD + zc + 0] = a1.x + zx1.x;
        zs[(b0 + 1) * ZPAD + zc + 1] = a1.y + zx1.y;
        zs[(b0 + 1) * ZPAD + zc + 2] = a1.z + zx1.z;
        zs[(b0 + 1) * ZPAD + zc + 3] = a1.w + zx1.w;
        __syncthreads();

        // gate math: thread handles (gb, gu) and (gb, gu+1)
        {
            float h2v[2];
#pragma unroll
            for (int q = 0; q < 2; q++) {
                int ul = gu + q;
                float zi = zs[gb * ZPAD + ul];
                float zf = zs[gb * ZPAD + 8 + ul];
                float zg = zs[gb * ZPAD + 16 + ul];
                float zo = zs[gb * ZPAD + 24 + ul];
                float ig = 1.f / (1.f + expf(-zi));
                float fg = 1.f / (1.f + expf(-zf));
                float og = 1.f / (1.f + expf(-zo));
                float c  = fmaf(fg, cs[gb * CPAD + ul], ig * zg);
                cs[gb * CPAD + ul] = c;
                float h = og * c;
                g_hbuf[(t + 1) & 1][(u_base + ul) * Bb + gb] = h;
                h2v[q] = h;
            }
            if (store_seq) {
                float2 st = { h2v[0], h2v[1] };
                *(float2*)&g_h1[((size_t)gb * Tt + t) * Uu + u_base + gu] = st;
            }
        }
        grid_sync();   // publishes h for the next step; protects SMEM reuse
    }
    // final h (t = T-1) is in g_hbuf[0]
}

// ---------------------------------------------------------------------------
// LayerNorm over last dim (1024) + tanh.
// mode 0: in/out = g_h1 [32768,1024] row-major, in place.
// mode 1: in = g_hbuf[0] transposed [u][b]; out = external [64,1024].
// ---------------------------------------------------------------------------
__global__ void __launch_bounds__(256) ln_tanh_kernel(
    int mode, float* __restrict__ outext,
    const float* __restrict__ gamma, const float* __restrict__ beta)
{
    const int row = blockIdx.x;
    const int tid = threadIdx.x;
    const float* in;
    size_t rs, us;
    if (mode == 0) { in = g_h1;          rs = Uu; us = 1;  }
    else           { in = &g_hbuf[0][0]; rs = 1;  us = Bb; }

    float v[4];
    float s = 0.f, sq = 0.f;
#pragma unroll
    for (int i = 0; i < 4; i++) {
        int u = tid + i * 256;
        v[i] = in[(size_t)row * rs + (size_t)u * us];
        s  += v[i];
        sq += v[i] * v[i];
    }
#pragma unroll
    for (int o = 16; o; o >>= 1) {
        s  += __shfl_xor_sync(0xffffffffu, s, o);
        sq += __shfl_xor_sync(0xffffffffu, sq, o);
    }
    __shared__ float ws[8], wq[8];
    __shared__ float s_mu, s_inv;
    if ((tid & 31) == 0) { ws[tid >> 5] = s; wq[tid >> 5] = sq; }
    __syncthreads();
    if (tid == 0) {
        float ts = 0.f, tq = 0.f;
#pragma unroll
        for (int i = 0; i < 8; i++) { ts += ws[i]; tq += wq[i]; }
        float mu  = ts * (1.f / 1024.f);
        float var = tq * (1.f / 1024.f) - mu * mu;
        s_mu  = mu;
        s_inv = rsqrtf(var + 1e-3f);
    }
    __syncthreads();
    float mu = s_mu, inv = s_inv;
#pragma unroll
    for (int i = 0; i < 4; i++) {
        int u = tid + i * 256;
        float y = tanhf((v[i] - mu) * inv * gamma[u] + beta[u]);
        if (mode == 0) g_h1[(size_t)row * Uu + u] = y;
        else           outext[(size_t)row * Uu + u] = y;
    }
}

// ---------------------------------------------------------------------------
// Launch: GEMM1 -> recur1 -> LN1(in place) -> GEMM2 -> recur2 -> LN2 -> out
// ---------------------------------------------------------------------------
extern "C" void kernel_launch(void* const* d_in, const int* in_sizes, int n_in,
                              void* d_out, int out_size)
{
    const float* x      = (const float*)d_in[0];
    const float* W1     = (const float*)d_in[1];
    const float* R1     = (const float*)d_in[2];
    const float* b1     = (const float*)d_in[3];
    const float* gamma1 = (const float*)d_in[4];
    const float* beta1  = (const float*)d_in[5];
    const float* W2     = (const float*)d_in[6];
    const float* R2     = (const float*)d_in[7];
    const float* b2     = (const float*)d_in[8];
    const float* gamma2 = (const float*)d_in[9];
    const float* beta2  = (const float*)d_in[10];
    float* out = (float*)d_out;

    cudaFuncSetAttribute(recur_kernel,
                         cudaFuncAttributeMaxDynamicSharedMemorySize, SMEM_DYN);

    dim3 gg(NG / 128, BT / 128);

    gemm_bias_kernel<Dd><<<gg, 256>>>(x, W1, b1, 0);            // zx1 = x@W1 + b1
    recur_kernel<<<RGRID, 256, SMEM_DYN>>>(R1, 1);              // h1 sequence
    ln_tanh_kernel<<<BT, 256>>>(0, nullptr, gamma1, beta1);     // LN+tanh in place
    gemm_bias_kernel<Uu><<<gg, 256>>>(nullptr, W2, b2, 1);      // zx2 = h1n@W2 + b2
    recur_kernel<<<RGRID, 256, SMEM_DYN>>>(R2, 0);              // h2 in g_hbuf[0]
    ln_tanh_kernel<<<Bb, 256>>>(1, out, gamma2, beta2);         // final LN+tanh
}